// round 1
// baseline (speedup 1.0000x reference)
#include <cuda_runtime.h>

#define NN 50000
#define EE 400000
#define HDIM 128          // HDE = H*DE
#define NHEAD 8
#define DEF 16            // out edge feats per head
#define DNF 16            // out node feats per head

// ---------------- scratch (device globals; no allocation allowed) ----------
__device__ float g_N1t[HDIM * HDIM];   // (W1@W_ni) transposed: [k][c]
__device__ float g_A2t[HDIM * HDIM];   // (W2@W_fij) transposed
__device__ float g_N3t[HDIM * HDIM];   // (W3@W_nj) transposed
__device__ float g_Wnt[HDIM * HDIM];   // W_node transposed
__device__ float g_wsum[DEF];          // column-sum of W_attn
__device__ float g_tsrc[NN * HDIM];
__device__ float g_tdst[NN * HDIM];
__device__ float g_hnode[NN * HDIM];
__device__ float g_a[EE * NHEAD];      // logits, then overwritten with exp(logits)
__device__ float g_den[NN * NHEAD];    // softmax denominators

// ---------------- init: zero den + out1 -------------------------------------
__global__ void k_init(float* __restrict__ out1) {
    int i = blockIdx.x * blockDim.x + threadIdx.x;
    if (i < NN * NHEAD) g_den[i] = 0.f;
    if (i < NN * DNF)   out1[i] = 0.f;
}

// ---------------- weight preprocessing --------------------------------------
// grid (128, 4), block 128. blockIdx.x = k, threadIdx.x = c, blockIdx.y = matrix
__global__ void k_weights(const float* __restrict__ W_edges,
                          const float* __restrict__ W_ni,
                          const float* __restrict__ W_nj,
                          const float* __restrict__ W_fij,
                          const float* __restrict__ W_node,
                          const float* __restrict__ W_attn) {
    int k = blockIdx.x;
    int c = threadIdx.x;
    int m = blockIdx.y;
    if (m == 0) {
        float acc = 0.f;
        for (int j = 0; j < 128; ++j) acc += W_edges[c * 384 + j] * W_ni[j * 128 + k];
        g_N1t[k * 128 + c] = acc;
    } else if (m == 1) {
        float acc = 0.f;
        for (int j = 0; j < 128; ++j) acc += W_edges[c * 384 + 128 + j] * W_fij[j * 128 + k];
        g_A2t[k * 128 + c] = acc;
    } else if (m == 2) {
        float acc = 0.f;
        for (int j = 0; j < 128; ++j) acc += W_edges[c * 384 + 256 + j] * W_nj[j * 128 + k];
        g_N3t[k * 128 + c] = acc;
    } else {
        g_Wnt[k * 128 + c] = W_node[c * 128 + k];
        if (k == 0 && c < DEF) {
            float s = 0.f;
            for (int h = 0; h < NHEAD; ++h) s += W_attn[h * DEF + c];
            g_wsum[c] = s;
        }
    }
}

// ---------------- register-blocked 64x128 fp32x2 GEMM core ------------------
// acc[i][j] = packed pair of fp32 accumulators for row r0+i, cols c0+2j,c0+2j+1
__device__ __forceinline__ void mm_tile(const float* __restrict__ as,
                                        const float* __restrict__ bs,
                                        int r0, int c0,
                                        unsigned long long (&acc)[4][4]) {
#pragma unroll 4
    for (int k = 0; k < 128; ++k) {
        const unsigned long long* bq =
            reinterpret_cast<const unsigned long long*>(bs + k * 128 + c0);
        unsigned long long b0 = bq[0], b1 = bq[1], b2 = bq[2], b3 = bq[3];
#pragma unroll
        for (int i = 0; i < 4; ++i) {
            float av = as[(r0 + i) * 128 + k];
            unsigned long long ad;
            asm("mov.b64 %0, {%1, %1};" : "=l"(ad) : "f"(av));
            asm("fma.rn.f32x2 %0, %1, %2, %0;" : "+l"(acc[i][0]) : "l"(ad), "l"(b0));
            asm("fma.rn.f32x2 %0, %1, %2, %0;" : "+l"(acc[i][1]) : "l"(ad), "l"(b1));
            asm("fma.rn.f32x2 %0, %1, %2, %0;" : "+l"(acc[i][2]) : "l"(ad), "l"(b2));
            asm("fma.rn.f32x2 %0, %1, %2, %0;" : "+l"(acc[i][3]) : "l"(ad), "l"(b3));
        }
    }
}

__device__ __forceinline__ void unpack2(unsigned long long v, float& lo, float& hi) {
    asm("mov.b64 {%0, %1}, %2;" : "=f"(lo), "=f"(hi) : "l"(v));
}

// ---------------- node-side GEMMs: t_src / t_dst / h_node -------------------
// grid (P, 3), block 256, dynamic smem = 128*128*4 + 64*128*4 = 98304 B
__global__ void __launch_bounds__(256, 2)
k_node_gemm(const float* __restrict__ nfeats, const float* __restrict__ b_node) {
    extern __shared__ float sm[];
    float* bs = sm;              // 128x128 weight (transposed layout [k][c])
    float* as = sm + 128 * 128;  // 64x128 node tile

    int m = blockIdx.y;
    const float* B = (m == 0) ? g_N1t : (m == 1 ? g_N3t : g_Wnt);
    float* OUT     = (m == 0) ? g_tsrc : (m == 1 ? g_tdst : g_hnode);

    int t = threadIdx.x;
    for (int i = t; i < 128 * 128 / 4; i += 256)
        ((float4*)bs)[i] = ((const float4*)B)[i];
    __syncthreads();

    int cg = t & 15, rg = t >> 4;
    int c0 = cg * 8, r0 = rg * 4;

    float badd[8];
#pragma unroll
    for (int j = 0; j < 8; ++j)
        badd[j] = (m == 2) ? __ldg(&b_node[c0 + j]) : 0.f;

    int ntiles = (NN + 63) / 64;
    for (int tile = blockIdx.x; tile < ntiles; tile += gridDim.x) {
        int n0 = tile * 64;
        for (int i = t; i < 64 * 128 / 4; i += 256) {
            int r = i >> 5, q = i & 31;
            int n = n0 + r;
            ((float4*)as)[i] = (n < NN) ? ((const float4*)(nfeats + (size_t)n * 128))[q]
                                        : make_float4(0.f, 0.f, 0.f, 0.f);
        }
        __syncthreads();

        unsigned long long acc[4][4];
#pragma unroll
        for (int i = 0; i < 4; ++i)
#pragma unroll
            for (int j = 0; j < 4; ++j) acc[i][j] = 0ull;

        mm_tile(as, bs, r0, c0, acc);

#pragma unroll
        for (int i = 0; i < 4; ++i) {
            int n = n0 + r0 + i;
            if (n < NN) {
                float* op = OUT + (size_t)n * 128 + c0;
#pragma unroll
                for (int j = 0; j < 4; ++j) {
                    float lo, hi;
                    unpack2(acc[i][j], lo, hi);
                    op[2 * j]     = lo + badd[2 * j];
                    op[2 * j + 1] = hi + badd[2 * j + 1];
                }
            }
        }
        __syncthreads();
    }
}

// ---------------- fused edge kernel ------------------------------------------
// t_e GEMM + gather(t_src,t_dst) + leakyReLU + bias + head-sum output + logits
// grid 296, block 256, dynamic smem = 98304 B
__global__ void __launch_bounds__(256, 2)
k_edge(const float* __restrict__ efeats, const int* __restrict__ src,
       const int* __restrict__ dst, const float* __restrict__ bias,
       float* __restrict__ out2) {
    extern __shared__ float sm[];
    float* bs = sm;
    float* as = sm + 128 * 128;

    int t = threadIdx.x;
    for (int i = t; i < 128 * 128 / 4; i += 256)
        ((float4*)bs)[i] = ((const float4*)g_A2t)[i];
    __syncthreads();

    int cg = t & 15, rg = t >> 4;
    int c0 = cg * 8, r0 = rg * 4;

    float bv[8];
#pragma unroll
    for (int j = 0; j < 8; ++j) bv[j] = __ldg(&bias[c0 + j]);

    const int ntiles = EE / 64;
    for (int tile = blockIdx.x; tile < ntiles; tile += gridDim.x) {
        int e0 = tile * 64;
        for (int i = t; i < 64 * 128 / 4; i += 256)
            ((float4*)as)[i] = ((const float4*)(efeats + (size_t)e0 * 128))[i];
        __syncthreads();

        unsigned long long acc[4][4];
#pragma unroll
        for (int i = 0; i < 4; ++i)
#pragma unroll
            for (int j = 0; j < 4; ++j) acc[i][j] = 0ull;

        mm_tile(as, bs, r0, c0, acc);

        // epilogue: gather + leaky + bias (into registers, as[] still live elsewhere)
        float fout[4][8];
#pragma unroll
        for (int i = 0; i < 4; ++i) {
            int e = e0 + r0 + i;
            int s  = __ldg(&src[e]);
            int dd = __ldg(&dst[e]);
            float4 ts0 = __ldg((const float4*)&g_tsrc[(size_t)s * 128 + c0]);
            float4 ts1 = __ldg((const float4*)&g_tsrc[(size_t)s * 128 + c0 + 4]);
            float4 td0 = __ldg((const float4*)&g_tdst[(size_t)dd * 128 + c0]);
            float4 td1 = __ldg((const float4*)&g_tdst[(size_t)dd * 128 + c0 + 4]);
            float addv[8] = {ts0.x + td0.x, ts0.y + td0.y, ts0.z + td0.z, ts0.w + td0.w,
                             ts1.x + td1.x, ts1.y + td1.y, ts1.z + td1.z, ts1.w + td1.w};
#pragma unroll
            for (int j = 0; j < 4; ++j) {
                float lo, hi;
                unpack2(acc[i][j], lo, hi);
                float f0 = lo + addv[2 * j];
                float f1 = hi + addv[2 * j + 1];
                f0 = (f0 > 0.f) ? f0 : 0.01f * f0;
                f1 = (f1 > 0.f) ? f1 : 0.01f * f1;
                fout[i][2 * j]     = f0 + bv[2 * j];
                fout[i][2 * j + 1] = f1 + bv[2 * j + 1];
            }
        }
        __syncthreads();  // all compute reads of as[] done

        // stash f_out tile in smem for cross-thread reductions
#pragma unroll
        for (int i = 0; i < 4; ++i)
#pragma unroll
            for (int j = 0; j < 8; ++j)
                as[(r0 + i) * 128 + c0 + j] = fout[i][j];
        __syncthreads();

        // out2[e][d] = sum_h f_out[e][h*16+d]
        for (int idx = t; idx < 64 * DEF; idx += 256) {
            int el = idx >> 4, d = idx & 15;
            float s = 0.f;
#pragma unroll
            for (int h = 0; h < NHEAD; ++h) s += as[el * 128 + h * DEF + d];
            out2[(size_t)(e0 + el) * DEF + d] = s;
        }
        // a[e][h] = sum_d f_out[e][h*16+d] * wsum[d]
        for (int idx = t; idx < 64 * NHEAD; idx += 256) {
            int el = idx >> 3, h = idx & 7;
            float s = 0.f;
#pragma unroll
            for (int d = 0; d < DEF; ++d)
                s += as[el * 128 + h * DEF + d] * __ldg(&g_wsum[d]);
            g_a[(size_t)(e0 + el) * NHEAD + h] = s;
        }
        __syncthreads();
    }
}

// ---------------- softmax denominator ---------------------------------------
__global__ void k_den(const int* __restrict__ dst) {
    int i = blockIdx.x * blockDim.x + threadIdx.x;
    if (i >= EE * NHEAD) return;
    float ex = expf(g_a[i]);       // logits are O(1); max-shift unnecessary
    g_a[i] = ex;
    int e = i >> 3, h = i & 7;
    atomicAdd(&g_den[(size_t)__ldg(&dst[e]) * NHEAD + h], ex);
}

// ---------------- message passing + head-sum output -------------------------
__global__ void k_msg(const int* __restrict__ src, const int* __restrict__ dst,
                      const float* __restrict__ norm, float* __restrict__ out1) {
    int gid = blockIdx.x * blockDim.x + threadIdx.x;
    int e = gid >> 4;
    int d = gid & 15;
    if (e >= EE) return;
    int s  = __ldg(&src[e]);
    int dd = __ldg(&dst[e]);
    float acc = 0.f;
#pragma unroll
    for (int h = 0; h < NHEAD; ++h) {
        float alpha = __fdividef(g_a[(size_t)e * NHEAD + h],
                                 g_den[(size_t)dd * NHEAD + h]);
        acc += alpha * g_hnode[(size_t)s * 128 + h * DNF + d];
    }
    atomicAdd(&out1[(size_t)dd * DNF + d], __ldg(&norm[e]) * acc);
}

// ---------------- launch ------------------------------------------------------
extern "C" void kernel_launch(void* const* d_in, const int* in_sizes, int n_in,
                              void* d_out, int out_size) {
    const float* nfeats  = (const float*)d_in[0];
    const float* efeats  = (const float*)d_in[1];
    const float* norm    = (const float*)d_in[2];
    const int*   src     = (const int*)d_in[3];
    const int*   dst     = (const int*)d_in[4];
    const float* W_ni    = (const float*)d_in[5];
    const float* W_nj    = (const float*)d_in[6];
    const float* W_fij   = (const float*)d_in[7];
    const float* W_edges = (const float*)d_in[8];
    const float* W_attn  = (const float*)d_in[9];
    const float* bias    = (const float*)d_in[10];
    const float* W_node  = (const float*)d_in[11];
    const float* b_node  = (const float*)d_in[12];

    float* out1 = (float*)d_out;          // h_out.sum(axis=1): [N,16]
    float* out2 = out1 + (size_t)NN * DNF; // f_out.sum(axis=1): [E,16]

    cudaFuncSetAttribute(k_node_gemm, cudaFuncAttributeMaxDynamicSharedMemorySize, 98304);
    cudaFuncSetAttribute(k_edge,      cudaFuncAttributeMaxDynamicSharedMemorySize, 98304);

    k_init<<<3125, 256>>>(out1);
    k_weights<<<dim3(128, 4), 128>>>(W_edges, W_ni, W_nj, W_fij, W_node, W_attn);
    k_node_gemm<<<dim3(99, 3), 256, 98304>>>(nfeats, b_node);
    k_edge<<<296, 256, 98304>>>(efeats, src, dst, bias, out2);
    k_den<<<(EE * NHEAD + 255) / 256, 256>>>(dst);
    k_msg<<<(EE * DNF + 255) / 256, 256>>>(src, dst, norm, out1);
}

// round 2
// speedup vs baseline: 1.1506x; 1.1506x over previous
#include <cuda_runtime.h>

#define NN 50000
#define EE 400000
#define NHEAD 8
#define DEF 16
#define DNF 16

// ---------------- scratch (device globals; no allocation allowed) ----------
__device__ float g_N1t[128 * 128];   // (W1@W_ni) transposed: [k][c]
__device__ float g_A2t[128 * 128];   // (W2@W_fij) transposed
__device__ float g_N3t[128 * 128];   // (W3@W_nj) transposed
__device__ float g_Wnt[128 * 128];   // W_node transposed
__device__ float g_wsum[DEF];        // column-sum of W_attn
__device__ float g_tsrc[NN * 128];
__device__ float g_tdst[NN * 128];
__device__ float g_hnode[NN * 128];
__device__ float g_a[EE * NHEAD];    // exp(logits)
__device__ float g_den[NN * NHEAD];  // softmax denominators

// ---------------- init: zero den + out1 -------------------------------------
__global__ void k_init(float* __restrict__ out1) {
    int i = blockIdx.x * blockDim.x + threadIdx.x;
    if (i < NN * NHEAD) g_den[i] = 0.f;
    if (i < NN * DNF)   out1[i] = 0.f;
}

// ---------------- weight preprocessing --------------------------------------
__global__ void k_weights(const float* __restrict__ W_edges,
                          const float* __restrict__ W_ni,
                          const float* __restrict__ W_nj,
                          const float* __restrict__ W_fij,
                          const float* __restrict__ W_node,
                          const float* __restrict__ W_attn) {
    int k = blockIdx.x;
    int c = threadIdx.x;
    int m = blockIdx.y;
    if (m == 0) {
        float acc = 0.f;
        for (int j = 0; j < 128; ++j) acc += W_edges[c * 384 + j] * W_ni[j * 128 + k];
        g_N1t[k * 128 + c] = acc;
    } else if (m == 1) {
        float acc = 0.f;
        for (int j = 0; j < 128; ++j) acc += W_edges[c * 384 + 128 + j] * W_fij[j * 128 + k];
        g_A2t[k * 128 + c] = acc;
    } else if (m == 2) {
        float acc = 0.f;
        for (int j = 0; j < 128; ++j) acc += W_edges[c * 384 + 256 + j] * W_nj[j * 128 + k];
        g_N3t[k * 128 + c] = acc;
    } else {
        g_Wnt[k * 128 + c] = W_node[c * 128 + k];
        if (k == 0 && c < DEF) {
            float s = 0.f;
            for (int h = 0; h < NHEAD; ++h) s += W_attn[h * DEF + c];
            g_wsum[c] = s;
        }
    }
}

// ---------------- 128x128 tile, 8x8 per-thread fp32x2 GEMM core -------------
__device__ __forceinline__ void mm128(const float* __restrict__ as,
                                      const float* __restrict__ bs,
                                      int r0, int c0,
                                      unsigned long long (&acc)[8][4]) {
#pragma unroll 4
    for (int k = 0; k < 128; ++k) {
        const ulonglong2* bq = reinterpret_cast<const ulonglong2*>(bs + k * 128 + c0);
        ulonglong2 p = bq[0];
        ulonglong2 q = bq[1];
#pragma unroll
        for (int i = 0; i < 8; ++i) {
            float av = as[(r0 + i) * 128 + k];
            unsigned long long ad;
            asm("mov.b64 %0, {%1, %1};" : "=l"(ad) : "f"(av));
            asm("fma.rn.f32x2 %0, %1, %2, %0;" : "+l"(acc[i][0]) : "l"(ad), "l"(p.x));
            asm("fma.rn.f32x2 %0, %1, %2, %0;" : "+l"(acc[i][1]) : "l"(ad), "l"(p.y));
            asm("fma.rn.f32x2 %0, %1, %2, %0;" : "+l"(acc[i][2]) : "l"(ad), "l"(q.x));
            asm("fma.rn.f32x2 %0, %1, %2, %0;" : "+l"(acc[i][3]) : "l"(ad), "l"(q.y));
        }
    }
}

__device__ __forceinline__ void unpack2(unsigned long long v, float& lo, float& hi) {
    asm("mov.b64 {%0, %1}, %2;" : "=f"(lo), "=f"(hi) : "l"(v));
}

// ---------------- node-side GEMMs: t_src / t_dst / h_node -------------------
// block 256, tile 128 nodes x 128 cols, dyn smem 128KB
__global__ void __launch_bounds__(256, 1)
k_node_gemm(const float* __restrict__ nfeats, const float* __restrict__ b_node) {
    extern __shared__ float sm[];
    float* bs = sm;              // 128x128 weight, [k][c]
    float* as = sm + 128 * 128;  // 128x128 node tile

    int m = blockIdx.y;
    const float* B = (m == 0) ? g_N1t : (m == 1 ? g_N3t : g_Wnt);
    float* OUT     = (m == 0) ? g_tsrc : (m == 1 ? g_tdst : g_hnode);

    int t = threadIdx.x;
    for (int i = t; i < 128 * 128 / 4; i += 256)
        ((float4*)bs)[i] = ((const float4*)B)[i];

    int cg = t & 15, rg = t >> 4;
    int c0 = cg * 8, r0 = rg * 8;

    float badd[8];
#pragma unroll
    for (int j = 0; j < 8; ++j)
        badd[j] = (m == 2) ? __ldg(&b_node[c0 + j]) : 0.f;

    int ntiles = (NN + 127) / 128;
    for (int tile = blockIdx.x; tile < ntiles; tile += gridDim.x) {
        int n0 = tile * 128;
        __syncthreads();  // prev-iter readers of as done (also covers bs first time)
        for (int i = t; i < 128 * 128 / 4; i += 256) {
            int r = i >> 5, qd = i & 31;
            int n = n0 + r;
            ((float4*)as)[i] = (n < NN) ? ((const float4*)(nfeats + (size_t)n * 128))[qd]
                                        : make_float4(0.f, 0.f, 0.f, 0.f);
        }
        __syncthreads();

        unsigned long long acc[8][4];
#pragma unroll
        for (int i = 0; i < 8; ++i)
#pragma unroll
            for (int j = 0; j < 4; ++j) acc[i][j] = 0ull;

        mm128(as, bs, r0, c0, acc);

#pragma unroll
        for (int i = 0; i < 8; ++i) {
            int n = n0 + r0 + i;
            if (n < NN) {
                float* op = OUT + (size_t)n * 128 + c0;
#pragma unroll
                for (int j = 0; j < 4; ++j) {
                    float lo, hi;
                    unpack2(acc[i][j], lo, hi);
                    op[2 * j]     = lo + badd[2 * j];
                    op[2 * j + 1] = hi + badd[2 * j + 1];
                }
            }
        }
    }
}

// ---------------- fused edge kernel ------------------------------------------
// t_e GEMM + gather + leakyReLU + bias + head-sum out2 + exp(logits) + den atomics
__global__ void __launch_bounds__(256, 1)
k_edge(const float* __restrict__ efeats, const int* __restrict__ src,
       const int* __restrict__ dst, const float* __restrict__ bias,
       float* __restrict__ out2) {
    extern __shared__ float sm[];
    float* bs = sm;
    float* as = sm + 128 * 128;

    int t = threadIdx.x;
    for (int i = t; i < 128 * 128 / 4; i += 256)
        ((float4*)bs)[i] = ((const float4*)g_A2t)[i];

    int cg = t & 15, rg = t >> 4;
    int c0 = cg * 8, r0 = rg * 8;

    float bv[8];
#pragma unroll
    for (int j = 0; j < 8; ++j) bv[j] = __ldg(&bias[c0 + j]);

    float ws[DEF];
#pragma unroll
    for (int d = 0; d < DEF; ++d) ws[d] = __ldg(&g_wsum[d]);

    const int ntiles = EE / 128;   // 3125 exact
    for (int tile = blockIdx.x; tile < ntiles; tile += gridDim.x) {
        int e0 = tile * 128;
        __syncthreads();  // prev-iter readers of as done
        for (int i = t; i < 128 * 128 / 4; i += 256)
            ((float4*)as)[i] = ((const float4*)(efeats + (size_t)e0 * 128))[i];
        __syncthreads();

        unsigned long long acc[8][4];
#pragma unroll
        for (int i = 0; i < 8; ++i)
#pragma unroll
            for (int j = 0; j < 4; ++j) acc[i][j] = 0ull;

        mm128(as, bs, r0, c0, acc);

        // epilogue: gather + leakyReLU + bias into registers
        float fout[8][8];
#pragma unroll
        for (int i = 0; i < 8; ++i) {
            int e = e0 + r0 + i;
            int s  = __ldg(&src[e]);
            int dd = __ldg(&dst[e]);
            float4 ts0 = __ldg((const float4*)&g_tsrc[(size_t)s * 128 + c0]);
            float4 ts1 = __ldg((const float4*)&g_tsrc[(size_t)s * 128 + c0 + 4]);
            float4 td0 = __ldg((const float4*)&g_tdst[(size_t)dd * 128 + c0]);
            float4 td1 = __ldg((const float4*)&g_tdst[(size_t)dd * 128 + c0 + 4]);
            float addv[8] = {ts0.x + td0.x, ts0.y + td0.y, ts0.z + td0.z, ts0.w + td0.w,
                             ts1.x + td1.x, ts1.y + td1.y, ts1.z + td1.z, ts1.w + td1.w};
#pragma unroll
            for (int j = 0; j < 4; ++j) {
                float lo, hi;
                unpack2(acc[i][j], lo, hi);
                float f0 = lo + addv[2 * j];
                float f1 = hi + addv[2 * j + 1];
                f0 = (f0 > 0.f) ? f0 : 0.01f * f0;
                f1 = (f1 > 0.f) ? f1 : 0.01f * f1;
                fout[i][2 * j]     = f0 + bv[2 * j];
                fout[i][2 * j + 1] = f1 + bv[2 * j + 1];
            }
        }
        __syncthreads();  // all mm128 reads of as[] done everywhere

        // stash f_out tile in smem for cross-thread reductions
#pragma unroll
        for (int i = 0; i < 8; ++i)
#pragma unroll
            for (int j = 0; j < 8; ++j)
                as[(r0 + i) * 128 + c0 + j] = fout[i][j];
        __syncthreads();

        // out2[e][d] = sum_h f_out[e][h*16+d]
#pragma unroll
        for (int idx = t; idx < 128 * DEF; idx += 256) {
            int el = idx >> 4, d = idx & 15;
            float s = 0.f;
#pragma unroll
            for (int h = 0; h < NHEAD; ++h) s += as[el * 128 + h * DEF + d];
            out2[(size_t)(e0 + el) * DEF + d] = s;
        }
        // exp(logit) + denominator accumulation (fused k_den)
#pragma unroll
        for (int idx = t; idx < 128 * NHEAD; idx += 256) {
            int el = idx >> 3, h = idx & 7;
            float s = 0.f;
#pragma unroll
            for (int d = 0; d < DEF; ++d)
                s += as[el * 128 + h * DEF + d] * ws[d];
            float ex = __expf(s);
            int e = e0 + el;
            g_a[(size_t)e * NHEAD + h] = ex;
            atomicAdd(&g_den[(size_t)__ldg(&dst[e]) * NHEAD + h], ex);
        }
    }
}

// ---------------- message passing + head-sum output -------------------------
__global__ void k_msg(const int* __restrict__ src, const int* __restrict__ dst,
                      const float* __restrict__ norm, float* __restrict__ out1) {
    int gid = blockIdx.x * blockDim.x + threadIdx.x;
    int e = gid >> 4;
    int d = gid & 15;
    if (e >= EE) return;
    int s  = __ldg(&src[e]);
    int dd = __ldg(&dst[e]);
    float acc = 0.f;
#pragma unroll
    for (int h = 0; h < NHEAD; ++h) {
        float alpha = __fdividef(g_a[(size_t)e * NHEAD + h],
                                 g_den[(size_t)dd * NHEAD + h]);
        acc += alpha * g_hnode[(size_t)s * 128 + h * DNF + d];
    }
    atomicAdd(&out1[(size_t)dd * DNF + d], __ldg(&norm[e]) * acc);
}

// ---------------- launch ------------------------------------------------------
extern "C" void kernel_launch(void* const* d_in, const int* in_sizes, int n_in,
                              void* d_out, int out_size) {
    const float* nfeats  = (const float*)d_in[0];
    const float* efeats  = (const float*)d_in[1];
    const float* norm    = (const float*)d_in[2];
    const int*   src     = (const int*)d_in[3];
    const int*   dst     = (const int*)d_in[4];
    const float* W_ni    = (const float*)d_in[5];
    const float* W_nj    = (const float*)d_in[6];
    const float* W_fij   = (const float*)d_in[7];
    const float* W_edges = (const float*)d_in[8];
    const float* W_attn  = (const float*)d_in[9];
    const float* bias    = (const float*)d_in[10];
    const float* W_node  = (const float*)d_in[11];
    const float* b_node  = (const float*)d_in[12];

    float* out1 = (float*)d_out;           // h_out.sum(axis=1): [N,16]
    float* out2 = out1 + (size_t)NN * DNF; // f_out.sum(axis=1): [E,16]

    cudaFuncSetAttribute(k_node_gemm, cudaFuncAttributeMaxDynamicSharedMemorySize, 131072);
    cudaFuncSetAttribute(k_edge,      cudaFuncAttributeMaxDynamicSharedMemorySize, 131072);

    k_init<<<3125, 256>>>(out1);
    k_weights<<<dim3(128, 4), 128>>>(W_edges, W_ni, W_nj, W_fij, W_node, W_attn);
    k_node_gemm<<<dim3(148, 3), 256, 131072>>>(nfeats, b_node);
    k_edge<<<148, 256, 131072>>>(efeats, src, dst, bias, out2);
    k_msg<<<(EE * DNF + 255) / 256, 256>>>(src, dst, norm, out1);
}

// round 4
// speedup vs baseline: 1.8631x; 1.6192x over previous
#include <cuda_runtime.h>
#include <cuda_bf16.h>
#include <cstring>
#include <cstdint>

#define NN 50000
#define EE 400000
#define NHEAD 8
#define DEF 16
#define DNF 16

// ---------------- device global scratch ------------------------------------
__device__ float g_N1t[128 * 128];   // (W1@W_ni)^T: [k][c]
__device__ float g_A2t[128 * 128];   // (W2@W_fij)^T
__device__ float g_N3t[128 * 128];   // (W3@W_nj)^T
__device__ float g_Wnt[128 * 128];   // W_node^T
__device__ float g_wsum[DEF];
// B operands as bf16 [n][k], row stride 136 elements
__device__ __nv_bfloat16 g_Bhi[4 * 128 * 136];
__device__ __nv_bfloat16 g_Blo[4 * 128 * 136];
__device__ float g_tsrc[NN * 128];
__device__ float g_tdst[NN * 128];
__device__ float g_hnode[NN * 128];
__device__ float g_a[EE * NHEAD];
__device__ float g_den[NN * NHEAD];

// ---------------- smem layout (bytes) ---------------------------------------
#define RSTRIDE 272            // 136 bf16 per row
#define A_BYTES (128 * RSTRIDE)   // 34816
#define SM_BIAS 0
#define SM_WS   512
#define SM_A    1024
#define SM_AHI  SM_A
#define SM_ALO  (SM_A + A_BYTES)        // 35840
#define SM_BHI  (SM_ALO + A_BYTES)      // 70656
#define SM_BLO  (SM_BHI + A_BYTES)      // 105472
#define SM_TOTAL (SM_BLO + A_BYTES)     // 140288
#define SM_FBUF SM_A                    // fp32 staging overlays A (67584 <= 69632)
#define FB_STRIDE 132

// ---------------- small kernels ----------------------------------------------
__global__ void k_init(float* __restrict__ out1) {
    int i = blockIdx.x * blockDim.x + threadIdx.x;
    if (i < NN * NHEAD) g_den[i] = 0.f;
    if (i < NN * DNF)   out1[i] = 0.f;
}

__global__ void k_weights(const float* __restrict__ W_edges,
                          const float* __restrict__ W_ni,
                          const float* __restrict__ W_nj,
                          const float* __restrict__ W_fij,
                          const float* __restrict__ W_node,
                          const float* __restrict__ W_attn) {
    int k = blockIdx.x, c = threadIdx.x, m = blockIdx.y;
    if (m == 0) {
        float acc = 0.f;
        for (int j = 0; j < 128; ++j) acc += W_edges[c * 384 + j] * W_ni[j * 128 + k];
        g_N1t[k * 128 + c] = acc;
    } else if (m == 1) {
        float acc = 0.f;
        for (int j = 0; j < 128; ++j) acc += W_edges[c * 384 + 128 + j] * W_fij[j * 128 + k];
        g_A2t[k * 128 + c] = acc;
    } else if (m == 2) {
        float acc = 0.f;
        for (int j = 0; j < 128; ++j) acc += W_edges[c * 384 + 256 + j] * W_nj[j * 128 + k];
        g_N3t[k * 128 + c] = acc;
    } else {
        g_Wnt[k * 128 + c] = W_node[c * 128 + k];
        if (k == 0 && c < DEF) {
            float s = 0.f;
            for (int h = 0; h < NHEAD; ++h) s += W_attn[h * DEF + c];
            g_wsum[c] = s;
        }
    }
}

// convert combined weights into bf16 hi/lo [n][k] stride-136 operands
__global__ void k_wconv() {
    int idx = blockIdx.x * blockDim.x + threadIdx.x;  // 65536
    int m = idx >> 14, r = idx & 16383;
    int n = r >> 7, k = r & 127;                      // B[n][k] = Wt[k][n]
    const float* srcs[4] = {g_N1t, g_A2t, g_N3t, g_Wnt};
    float w = srcs[m][k * 128 + n];
    __nv_bfloat16 h = __float2bfloat16(w);
    __nv_bfloat16 l = __float2bfloat16(w - __bfloat162float(h));
    g_Bhi[m * 128 * 136 + n * 136 + k] = h;
    g_Blo[m * 128 * 136 + n * 136 + k] = l;
}

// ---------------- fp32 -> bf16 hi/lo tile stage ------------------------------
__device__ __forceinline__ void split8(const float4 v0, const float4 v1, uint4& H, uint4& L) {
    float x[8] = {v0.x, v0.y, v0.z, v0.w, v1.x, v1.y, v1.z, v1.w};
    unsigned hu[4], lu[4];
#pragma unroll
    for (int j = 0; j < 4; ++j) {
        __nv_bfloat162 hp = __floats2bfloat162_rn(x[2 * j], x[2 * j + 1]);
        float ra = x[2 * j]     - __low2float(hp);
        float rb = x[2 * j + 1] - __high2float(hp);
        __nv_bfloat162 lp = __floats2bfloat162_rn(ra, rb);
        memcpy(&hu[j], &hp, 4);
        memcpy(&lu[j], &lp, 4);
    }
    H = make_uint4(hu[0], hu[1], hu[2], hu[3]);
    L = make_uint4(lu[0], lu[1], lu[2], lu[3]);
}

__device__ __forceinline__ void load_tile(char* smc, const float* __restrict__ srcp,
                                          int base, int limit, int t) {
    for (int i = t; i < 2048; i += 256) {
        int row = i >> 4, col = (i & 15) * 8;
        int gr = base + row;
        float4 v0, v1;
        if (gr < limit) {
            v0 = __ldg((const float4*)(srcp + (size_t)gr * 128 + col));
            v1 = __ldg((const float4*)(srcp + (size_t)gr * 128 + col + 4));
        } else {
            v0 = make_float4(0.f, 0.f, 0.f, 0.f); v1 = v0;
        }
        uint4 H, L;
        split8(v0, v1, H, L);
        *(uint4*)(smc + SM_AHI + row * RSTRIDE + col * 2) = H;
        *(uint4*)(smc + SM_ALO + row * RSTRIDE + col * 2) = L;
    }
}

// ---------------- mma.sync bf16 split GEMM core ------------------------------
__device__ __forceinline__ void mma16816(float (&d)[4], const uint32_t (&a)[4],
                                         const uint32_t (&b)[2]) {
    asm("mma.sync.aligned.m16n8k16.row.col.f32.bf16.bf16.f32 "
        "{%0,%1,%2,%3}, {%4,%5,%6,%7}, {%8,%9}, {%0,%1,%2,%3};"
        : "+f"(d[0]), "+f"(d[1]), "+f"(d[2]), "+f"(d[3])
        : "r"(a[0]), "r"(a[1]), "r"(a[2]), "r"(a[3]), "r"(b[0]), "r"(b[1]));
}

__device__ __forceinline__ uint32_t lds32(const char* base, int r, int k) {
    return *(const uint32_t*)(base + r * RSTRIDE + k * 2);
}

// block tile 128x128, warp tile 64x32; acc[mt][nt][4]
__device__ __forceinline__ void mm_split(char* smc, int warp, int lane,
                                         float (&acc)[4][4][4]) {
    int warpm = warp & 1, warpn = warp >> 1;
    int q = lane >> 2, tid = lane & 3;
    const char* Ahi = smc + SM_AHI;
    const char* Alo = smc + SM_ALO;
    const char* Bhi = smc + SM_BHI;
    const char* Blo = smc + SM_BLO;

#pragma unroll
    for (int mt = 0; mt < 4; ++mt)
#pragma unroll
        for (int nt = 0; nt < 4; ++nt)
#pragma unroll
            for (int j = 0; j < 4; ++j) acc[mt][nt][j] = 0.f;

#pragma unroll
    for (int k0 = 0; k0 < 8; ++k0) {
        int kk = k0 * 16 + 2 * tid;
        uint32_t ahi[4][4], alo[4][4], bhi[4][2], blo[4][2];
#pragma unroll
        for (int mt = 0; mt < 4; ++mt) {
            int r = warpm * 64 + mt * 16 + q;
            ahi[mt][0] = lds32(Ahi, r, kk);
            ahi[mt][1] = lds32(Ahi, r + 8, kk);
            ahi[mt][2] = lds32(Ahi, r, kk + 8);
            ahi[mt][3] = lds32(Ahi, r + 8, kk + 8);
            alo[mt][0] = lds32(Alo, r, kk);
            alo[mt][1] = lds32(Alo, r + 8, kk);
            alo[mt][2] = lds32(Alo, r, kk + 8);
            alo[mt][3] = lds32(Alo, r + 8, kk + 8);
        }
#pragma unroll
        for (int nt = 0; nt < 4; ++nt) {
            int n = warpn * 32 + nt * 8 + q;
            bhi[nt][0] = lds32(Bhi, n, kk);
            bhi[nt][1] = lds32(Bhi, n, kk + 8);
            blo[nt][0] = lds32(Blo, n, kk);
            blo[nt][1] = lds32(Blo, n, kk + 8);
        }
        // pass 1: hi*hi ; pass 2: hi*lo ; pass 3: lo*hi
#pragma unroll
        for (int mt = 0; mt < 4; ++mt)
#pragma unroll
            for (int nt = 0; nt < 4; ++nt) mma16816(acc[mt][nt], ahi[mt], bhi[nt]);
#pragma unroll
        for (int mt = 0; mt < 4; ++mt)
#pragma unroll
            for (int nt = 0; nt < 4; ++nt) mma16816(acc[mt][nt], ahi[mt], blo[nt]);
#pragma unroll
        for (int mt = 0; mt < 4; ++mt)
#pragma unroll
            for (int nt = 0; nt < 4; ++nt) mma16816(acc[mt][nt], alo[mt], bhi[nt]);
    }
}

__device__ __forceinline__ void dump_acc(char* smc, int warp, int lane,
                                         const float (&acc)[4][4][4]) {
    int warpm = warp & 1, warpn = warp >> 1;
    int q = lane >> 2, tid = lane & 3;
    float* fb = (float*)(smc + SM_FBUF);
#pragma unroll
    for (int mt = 0; mt < 4; ++mt) {
        int r = warpm * 64 + mt * 16 + q;
#pragma unroll
        for (int nt = 0; nt < 4; ++nt) {
            int c = warpn * 32 + nt * 8 + 2 * tid;
            *(float2*)&fb[r * FB_STRIDE + c]       = make_float2(acc[mt][nt][0], acc[mt][nt][1]);
            *(float2*)&fb[(r + 8) * FB_STRIDE + c] = make_float2(acc[mt][nt][2], acc[mt][nt][3]);
        }
    }
}

// ---------------- node GEMMs -------------------------------------------------
__global__ void __launch_bounds__(256, 1)
k_node_mma(const float* __restrict__ nfeats, const float* __restrict__ b_node) {
    extern __shared__ char smc[];
    int t = threadIdx.x, warp = t >> 5, lane = t & 31;
    int m = blockIdx.y;
    int mat = (m == 0) ? 0 : (m == 1 ? 2 : 3);
    float* OUT = (m == 0) ? g_tsrc : (m == 1 ? g_tdst : g_hnode);

    const uint4* bh = (const uint4*)(g_Bhi + mat * 128 * 136);
    const uint4* bl = (const uint4*)(g_Blo + mat * 128 * 136);
    for (int i = t; i < 2176; i += 256) {
        ((uint4*)(smc + SM_BHI))[i] = bh[i];
        ((uint4*)(smc + SM_BLO))[i] = bl[i];
    }
    float* bias_s = (float*)(smc + SM_BIAS);
    for (int i = t; i < 128; i += 256) bias_s[i] = (m == 2) ? __ldg(&b_node[i]) : 0.f;

    int ntiles = (NN + 127) / 128;
    for (int tile = blockIdx.x; tile < ntiles; tile += gridDim.x) {
        int n0 = tile * 128;
        load_tile(smc, nfeats, n0, NN, t);
        __syncthreads();
        float acc[4][4][4];
        mm_split(smc, warp, lane, acc);
        __syncthreads();        // all LDS reads of A done before fbuf overlay
        dump_acc(smc, warp, lane, acc);
        __syncthreads();
        // epilogue: row per thread pair
        int n = n0 + (t >> 1);
        if (n < NN) {
            int c0 = (t & 1) * 64;
            const float* frow = (float*)(smc + SM_FBUF) + (t >> 1) * FB_STRIDE + c0;
            float* op = OUT + (size_t)n * 128 + c0;
#pragma unroll
            for (int j = 0; j < 16; ++j) {
                float4 v = *(const float4*)(frow + j * 4);
                v.x += bias_s[c0 + j * 4];
                v.y += bias_s[c0 + j * 4 + 1];
                v.z += bias_s[c0 + j * 4 + 2];
                v.w += bias_s[c0 + j * 4 + 3];
                ((float4*)op)[j] = v;
            }
        }
        __syncthreads();        // epilogue reads done before next load_tile
    }
}

// ---------------- fused edge kernel ------------------------------------------
__global__ void __launch_bounds__(256, 1)
k_edge_mma(const float* __restrict__ efeats, const int* __restrict__ src,
           const int* __restrict__ dst, const float* __restrict__ bias,
           float* __restrict__ out2) {
    extern __shared__ char smc[];
    int t = threadIdx.x, warp = t >> 5, lane = t & 31;

    const uint4* bh = (const uint4*)(g_Bhi + 1 * 128 * 136);
    const uint4* bl = (const uint4*)(g_Blo + 1 * 128 * 136);
    for (int i = t; i < 2176; i += 256) {
        ((uint4*)(smc + SM_BHI))[i] = bh[i];
        ((uint4*)(smc + SM_BLO))[i] = bl[i];
    }
    float* bias_s = (float*)(smc + SM_BIAS);
    float* ws_s   = (float*)(smc + SM_WS);
    for (int i = t; i < 128; i += 256) bias_s[i] = __ldg(&bias[i]);
    if (t < DEF) ws_s[t] = g_wsum[t];

    const int ntiles = EE / 128;   // 3125 exact
    for (int tile = blockIdx.x; tile < ntiles; tile += gridDim.x) {
        int e0 = tile * 128;
        load_tile(smc, efeats, e0, 0x7fffffff, t);
        __syncthreads();
        float acc[4][4][4];
        mm_split(smc, warp, lane, acc);
        __syncthreads();
        dump_acc(smc, warp, lane, acc);
        __syncthreads();

        // epilogue: 2 threads per edge row (halves of 128 cols)
        int e = e0 + (t >> 1);
        int half = t & 1;
        int c0 = half * 64, h0 = half * 4;
        int s  = __ldg(&src[e]);
        int dd = __ldg(&dst[e]);
        const float* frow = (float*)(smc + SM_FBUF) + (t >> 1) * FB_STRIDE + c0;
        const float4* tsp = (const float4*)(g_tsrc + (size_t)s * 128 + c0);
        const float4* tdp = (const float4*)(g_tdst + (size_t)dd * 128 + c0);

        float pd[16];
#pragma unroll
        for (int d = 0; d < 16; ++d) pd[d] = 0.f;
        float ex[4];
#pragma unroll
        for (int hl = 0; hl < 4; ++hl) {
            float lgv = 0.f;
#pragma unroll
            for (int j = 0; j < 4; ++j) {
                float4 dv = *(const float4*)(frow + hl * 16 + j * 4);
                float4 a4 = __ldg(tsp + hl * 4 + j);
                float4 b4 = __ldg(tdp + hl * 4 + j);
                int cb = c0 + hl * 16 + j * 4;
                float v0 = dv.x + a4.x + b4.x;
                float v1 = dv.y + a4.y + b4.y;
                float v2 = dv.z + a4.z + b4.z;
                float v3 = dv.w + a4.w + b4.w;
                v0 = (v0 > 0.f) ? v0 : 0.01f * v0;
                v1 = (v1 > 0.f) ? v1 : 0.01f * v1;
                v2 = (v2 > 0.f) ? v2 : 0.01f * v2;
                v3 = (v3 > 0.f) ? v3 : 0.01f * v3;
                v0 += bias_s[cb];
                v1 += bias_s[cb + 1];
                v2 += bias_s[cb + 2];
                v3 += bias_s[cb + 3];
                pd[j * 4]     += v0;
                pd[j * 4 + 1] += v1;
                pd[j * 4 + 2] += v2;
                pd[j * 4 + 3] += v3;
                lgv += v0 * ws_s[j * 4] + v1 * ws_s[j * 4 + 1]
                     + v2 * ws_s[j * 4 + 2] + v3 * ws_s[j * 4 + 3];
            }
            ex[hl] = __expf(lgv);
        }
        // combine head-sum partials across the thread pair
#pragma unroll
        for (int d = 0; d < 16; ++d) pd[d] += __shfl_xor_sync(0xffffffffu, pd[d], 1);
        if (!half) {
#pragma unroll
            for (int qj = 0; qj < 4; ++qj)
                ((float4*)(out2 + (size_t)e * DEF))[qj] =
                    make_float4(pd[qj * 4], pd[qj * 4 + 1], pd[qj * 4 + 2], pd[qj * 4 + 3]);
        }
        ((float4*)g_a)[(size_t)e * 2 + half] = make_float4(ex[0], ex[1], ex[2], ex[3]);
#pragma unroll
        for (int hl = 0; hl < 4; ++hl)
            atomicAdd(&g_den[(size_t)dd * NHEAD + h0 + hl], ex[hl]);
        __syncthreads();
    }
}

// ---------------- message passing --------------------------------------------
__global__ void k_msg(const int* __restrict__ src, const int* __restrict__ dst,
                      const float* __restrict__ norm, float* __restrict__ out1) {
    int gid = blockIdx.x * blockDim.x + threadIdx.x;
    int e = gid >> 4, d = gid & 15;
    if (e >= EE) return;
    int s  = __ldg(&src[e]);
    int dd = __ldg(&dst[e]);
    float acc = 0.f;
#pragma unroll
    for (int h = 0; h < NHEAD; ++h) {
        float alpha = __fdividef(g_a[(size_t)e * NHEAD + h],
                                 g_den[(size_t)dd * NHEAD + h]);
        acc += alpha * g_hnode[(size_t)s * 128 + h * DNF + d];
    }
    atomicAdd(&out1[(size_t)dd * DNF + d], __ldg(&norm[e]) * acc);
}

// ---------------- launch ------------------------------------------------------
extern "C" void kernel_launch(void* const* d_in, const int* in_sizes, int n_in,
                              void* d_out, int out_size) {
    const float* nfeats  = (const float*)d_in[0];
    const float* efeats  = (const float*)d_in[1];
    const float* norm    = (const float*)d_in[2];
    const int*   src     = (const int*)d_in[3];
    const int*   dst     = (const int*)d_in[4];
    const float* W_ni    = (const float*)d_in[5];
    const float* W_nj    = (const float*)d_in[6];
    const float* W_fij   = (const float*)d_in[7];
    const float* W_edges = (const float*)d_in[8];
    const float* W_attn  = (const float*)d_in[9];
    const float* bias    = (const float*)d_in[10];
    const float* W_node  = (const float*)d_in[11];
    const float* b_node  = (const float*)d_in[12];

    float* out1 = (float*)d_out;
    float* out2 = out1 + (size_t)NN * DNF;

    cudaFuncSetAttribute(k_node_mma, cudaFuncAttributeMaxDynamicSharedMemorySize, SM_TOTAL);
    cudaFuncSetAttribute(k_edge_mma, cudaFuncAttributeMaxDynamicSharedMemorySize, SM_TOTAL);

    k_init<<<3125, 256>>>(out1);
    k_weights<<<dim3(128, 4), 128>>>(W_edges, W_ni, W_nj, W_fij, W_node, W_attn);
    k_wconv<<<256, 256>>>();
    k_node_mma<<<dim3(148, 3), 256, SM_TOTAL>>>(nfeats, b_node);
    k_edge_mma<<<148, 256, SM_TOTAL>>>(efeats, src, dst, bias, out2);
    k_msg<<<(EE * DNF + 255) / 256, 256>>>(src, dst, norm, out1);
}